// round 6
// baseline (speedup 1.0000x reference)
#include <cuda_runtime.h>
#include <cuda_fp16.h>
#include <mma.h>
#include <cstdint>

using namespace nvcuda;

// Scratch (__device__ globals; runtime alloc forbidden)
__device__ __half g_xa [14680064];  // [64 j1][1024 b][224 kpad]   fp16
__device__ __half g_k1t[14680064];  // [64 j1][1024 l1][224 kpad]  fp16
__device__ __half g_k3t[16777216];  // [64 j3][256 l3pad][1024 k3] fp16
__device__ __half g_h1p[67108864];  // [64 j1][16 r][64 p2][1024 b] fp16
__device__ __half g_h2r[67108864];  // [64 j3][1024 b][1024 k3]     fp16

__device__ __forceinline__ uint32_t smem_u32(const void* p) {
    uint32_t a;
    asm("{ .reg .u64 t; cvta.to.shared.u64 t, %1; cvt.u32.u64 %0, t; }"
        : "=r"(a) : "l"(p));
    return a;
}
__device__ __forceinline__ void cpa(uint32_t d, const void* s) {
    asm volatile("cp.async.cg.shared.global [%0], [%1], 16;" :: "r"(d), "l"(s));
}
__device__ __forceinline__ void cpcommit() { asm volatile("cp.async.commit_group;" ::: "memory"); }
__device__ __forceinline__ void cpwait0()  { asm volatile("cp.async.wait_group 0;" ::: "memory"); }
__device__ __forceinline__ void cpwait1()  { asm volatile("cp.async.wait_group 1;" ::: "memory"); }

// k-chunk buffers: row stride 56 halves (112B) -> LDSM banks (28*r)%32 all
// distinct per 8-row phase => conflict-free fragment loads.
#define LDM       56
#define ROWB      112
#define ABUF(buf) ((buf) * 14336)
#define BBUF(buf) (28672 + (buf) * 14336)
// g1 A-resident: stride 232 halves (464B): (116*r)%32 = {0,20,8,28,16,4,24,12} ok
#define ALDM      232
#define AROWB     464
#define G1_BBUF(buf) (59392 + (buf) * 14336)   // A region [0, 59392)

// ------------------------- pre-kernels ------------------------------------
__global__ __launch_bounds__(256) void gather_x(const float* __restrict__ x) {
    const int b = blockIdx.x;
    const int j1 = blockIdx.y * 8 + (threadIdx.x >> 5);
    const int lane = threadIdx.x & 31;
    const int bx = j1 >> 3, by = j1 & 7;
    const float* xr = x + b * 12800;
    __half* dst = g_xa + (j1 * 1024 + b) * 224;
    for (int k = lane; k < 224; k += 32) {
        float v = 0.0f;
        if (k < 200) {
            int q = k >> 1, c = k & 1;
            int wx = q / 10, wy = q - wx * 10;
            v = xr[((bx * 10 + wx) * 80 + by * 10 + wy) * 2 + c];
        }
        dst[k] = __float2half_rn(v);
    }
}
__global__ void transpose_k1(const float* __restrict__ k1) {
    __shared__ float t[32][33];
    const int j1 = blockIdx.z, l0 = blockIdx.x * 32, k0 = blockIdx.y * 32;
    const int tx = threadIdx.x, ty = threadIdx.y;
#pragma unroll
    for (int r = 0; r < 32; r += 8) {
        int k = k0 + ty + r;
        t[ty + r][tx] = (k < 200) ? k1[(j1 * 200 + k) * 1024 + l0 + tx] : 0.0f;
    }
    __syncthreads();
#pragma unroll
    for (int r = 0; r < 32; r += 8)
        g_k1t[(j1 * 1024 + l0 + ty + r) * 224 + k0 + tx] = __float2half_rn(t[tx][ty + r]);
}
__global__ void transpose_k3(const float* __restrict__ k3) {
    __shared__ float t[32][33];
    const int j3 = blockIdx.z, k0 = blockIdx.x * 32, l0 = blockIdx.y * 32;
    const int tx = threadIdx.x, ty = threadIdx.y;
#pragma unroll
    for (int r = 0; r < 32; r += 8) {
        int l = l0 + tx, k = k0 + ty + r;
        t[ty + r][tx] = (l < 200) ? k3[(j3 * 1024 + k) * 200 + l] : 0.0f;
    }
    __syncthreads();
#pragma unroll
    for (int r = 0; r < 32; r += 8)
        g_k3t[(j3 * 256 + l0 + ty + r) * 1024 + k0 + tx] = __float2half_rn(t[tx][ty + r]);
}

// ------------------------- GEMM1: A-resident, B double-buffered ------------
__global__ __launch_bounds__(256, 2) void g1(const float* __restrict__ b1) {
    extern __shared__ __align__(16) char dsm[];
    const int tid = threadIdx.x, wid = tid >> 5;
    const int wr = wid >> 1, wc = wid & 1;
    const int j1 = blockIdx.z, n0 = blockIdx.x * 128, m0 = blockIdx.y * 128;
    const uint32_t sbase = smem_u32(dsm);

    const __half* aS = g_xa  + (j1 * 1024 + m0) * 224;
    const __half* bS = g_k1t + (j1 * 1024 + n0) * 224;

    wmma::fragment<wmma::accumulator, 16, 16, 16, float> acc[2][4];
#pragma unroll
    for (int i = 0; i < 2; i++)
#pragma unroll
        for (int j = 0; j < 4; j++) wmma::fill_fragment(acc[i][j], 0.0f);

    // load ALL of A (128 x 224) + B chunk 0; group 0
    for (int i = tid; i < 3584; i += 256) {
        int row = i / 28, seg = i % 28;
        cpa(sbase + row * AROWB + seg * 16, aS + row * 224 + seg * 8);
    }
    for (int i = tid; i < 512; i += 256) {
        int row = i >> 2, seg = i & 3;
        cpa(sbase + G1_BBUF(0) + row * ROWB + seg * 16, bS + row * 224 + seg * 8);
    }
    cpcommit();

    const __half* As = (const __half*)dsm;
    for (int c = 0; c < 7; c++) {
        const int buf = c & 1;
        if (c + 1 < 7) {
            const int nb = (c + 1) & 1, k0 = (c + 1) * 32;
            for (int i = tid; i < 512; i += 256) {
                int row = i >> 2, seg = i & 3;
                cpa(sbase + G1_BBUF(nb) + row * ROWB + seg * 16,
                    bS + row * 224 + k0 + seg * 8);
            }
            cpcommit();
            cpwait1();
        } else {
            cpwait0();
        }
        __syncthreads();

        const __half* Bs = (const __half*)(dsm + G1_BBUF(buf));
#pragma unroll
        for (int kk = 0; kk < 32; kk += 16) {
            wmma::fragment<wmma::matrix_a, 16, 16, 16, __half, wmma::row_major> af[2];
            wmma::fragment<wmma::matrix_b, 16, 16, 16, __half, wmma::col_major> bf[4];
#pragma unroll
            for (int i = 0; i < 2; i++)
                wmma::load_matrix_sync(af[i], As + (wr * 32 + i * 16) * ALDM + c * 32 + kk, ALDM);
#pragma unroll
            for (int j = 0; j < 4; j++)
                wmma::load_matrix_sync(bf[j], Bs + (wc * 64 + j * 16) * LDM + kk, LDM);
#pragma unroll
            for (int i = 0; i < 2; i++)
#pragma unroll
                for (int j = 0; j < 4; j++)
                    wmma::mma_sync(acc[i][j], af[i], bf[j], acc[i][j]);
        }
        __syncthreads();
    }

    float* stage = (float*)dsm;
#pragma unroll
    for (int h = 0; h < 2; ++h) {
        if (wc == h) {
#pragma unroll
            for (int i = 0; i < 2; i++)
#pragma unroll
                for (int j = 0; j < 4; j++)
                    wmma::store_matrix_sync(
                        stage + (wr * 32 + i * 16) * 68 + j * 16,
                        acc[i][j], 68, wmma::mem_row_major);
        }
        __syncthreads();
        for (int e = tid; e < 8192; e += 256) {
            int cc = e >> 7, row = e & 127;
            int l1 = n0 + h * 64 + cc;
            float v = stage[row * 68 + cc] + b1[(j1 << 10) + l1];
            g_h1p[((j1 * 16 + (l1 & 15)) * 64 + (l1 >> 4)) * 1024 + m0 + row] =
                __float2half_rn(v);
        }
        __syncthreads();
    }
}

// ------------------------- GEMM2 (fp32 math, fp16 I/O) ---------------------
__global__ __launch_bounds__(128) void g2(const float* __restrict__ k2,
                                          const float* __restrict__ b2) {
    const int j2 = blockIdx.x, tid = threadIdx.x;
    __shared__ float wgt[256];
    __shared__ float bias[16];
    reinterpret_cast<float2*>(wgt)[tid] =
        reinterpret_cast<const float2*>(k2 + j2 * 256)[tid];
    if (tid < 16) bias[tid] = b2[j2 * 16 + tid];
    __syncthreads();

    const int r = j2 >> 8, j1 = (j2 >> 2) & 63, p2hi = j2 & 3;
    const int b = blockIdx.y * 128 + tid;
    const __half* src = g_h1p + ((j1 * 16 + r) * 64 + p2hi * 16) * 1024 + b;
    float in[16];
#pragma unroll
    for (int k = 0; k < 16; k++) in[k] = __half2float(src[k * 1024]);
    float out[16];
#pragma unroll
    for (int l = 0; l < 16; l++) out[l] = bias[l];
#pragma unroll
    for (int k = 0; k < 16; k++) {
        float a = in[k];
#pragma unroll
        for (int l = 0; l < 16; l++) out[l] += a * wgt[k * 16 + l];
    }
    __half2 ph[8];
#pragma unroll
    for (int q = 0; q < 8; q++)
        ph[q] = __floats2half2_rn(out[2 * q], out[2 * q + 1]);
    __half* dp = g_h2r + ((size_t)(r * 4 + (j1 >> 4)) * 1024 + b) * 1024 +
                 (j1 & 15) * 64 + p2hi * 16;
    reinterpret_cast<uint4*>(dp)[0] = reinterpret_cast<uint4*>(ph)[0];
    reinterpret_cast<uint4*>(dp)[1] = reinterpret_cast<uint4*>(ph)[1];
}

// ------------------------- GEMM3a: n-tile [0,128) -------------------------
__global__ __launch_bounds__(256, 2) void g3a(const float* __restrict__ b3,
                                              float* __restrict__ out) {
    extern __shared__ __align__(16) char dsm[];
    const int tid = threadIdx.x, wid = tid >> 5;
    const int wr = wid >> 1, wc = wid & 1;
    const int j3 = blockIdx.z, m0 = blockIdx.y * 128;
    const uint32_t sbase = smem_u32(dsm);

    const __half* aS = g_h2r + ((size_t)(j3 * 1024 + m0)) * 1024;
    const __half* bS = g_k3t + ((size_t)(j3 * 256)) * 1024;

    wmma::fragment<wmma::accumulator, 16, 16, 16, float> acc[2][4];
#pragma unroll
    for (int i = 0; i < 2; i++)
#pragma unroll
        for (int j = 0; j < 4; j++) wmma::fill_fragment(acc[i][j], 0.0f);

    for (int i = tid; i < 512; i += 256) {
        int row = i >> 2, seg = i & 3;
        cpa(sbase + ABUF(0) + row * ROWB + seg * 16, aS + row * 1024 + seg * 8);
        cpa(sbase + BBUF(0) + row * ROWB + seg * 16, bS + row * 1024 + seg * 8);
    }
    cpcommit();

    for (int c = 0; c < 32; c++) {
        const int buf = c & 1;
        if (c + 1 < 32) {
            const int nb = (c + 1) & 1, k0 = (c + 1) * 32;
            for (int i = tid; i < 512; i += 256) {
                int row = i >> 2, seg = i & 3;
                cpa(sbase + ABUF(nb) + row * ROWB + seg * 16,
                    aS + row * 1024 + k0 + seg * 8);
                cpa(sbase + BBUF(nb) + row * ROWB + seg * 16,
                    bS + row * 1024 + k0 + seg * 8);
            }
            cpcommit();
            cpwait1();
        } else {
            cpwait0();
        }
        __syncthreads();

        const __half* As = (const __half*)(dsm + ABUF(buf));
        const __half* Bs = (const __half*)(dsm + BBUF(buf));
#pragma unroll
        for (int kk = 0; kk < 32; kk += 16) {
            wmma::fragment<wmma::matrix_a, 16, 16, 16, __half, wmma::row_major> af[2];
            wmma::fragment<wmma::matrix_b, 16, 16, 16, __half, wmma::col_major> bf[4];
#pragma unroll
            for (int i = 0; i < 2; i++)
                wmma::load_matrix_sync(af[i], As + (wr * 32 + i * 16) * LDM + kk, LDM);
#pragma unroll
            for (int j = 0; j < 4; j++)
                wmma::load_matrix_sync(bf[j], Bs + (wc * 64 + j * 16) * LDM + kk, LDM);
#pragma unroll
            for (int i = 0; i < 2; i++)
#pragma unroll
                for (int j = 0; j < 4; j++)
                    wmma::mma_sync(acc[i][j], af[i], bf[j], acc[i][j]);
        }
        __syncthreads();
    }

    float* stage = (float*)dsm;
    const int b2x = j3 >> 3, b2y = j3 & 7;
#pragma unroll
    for (int h = 0; h < 2; ++h) {
        if (wc == h) {
#pragma unroll
            for (int i = 0; i < 2; i++)
#pragma unroll
                for (int j = 0; j < 4; j++)
                    wmma::store_matrix_sync(
                        stage + (wr * 32 + i * 16) * 68 + j * 16,
                        acc[i][j], 68, wmma::mem_row_major);
        }
        __syncthreads();
        for (int e = tid; e < 8192; e += 256) {
            int cc = e & 63, row = e >> 6;
            int l3 = h * 64 + cc;
            float v = stage[row * 68 + cc] + b3[j3 * 200 + l3];
            int q = l3 >> 1, c = l3 & 1;
            int w2x = q / 10, w2y = q - w2x * 10;
            out[(m0 + row) * 12800 +
                ((b2x * 10 + w2x) * 80 + b2y * 10 + w2y) * 2 + c] = v;
        }
        __syncthreads();
    }
}

// ------------------------- GEMM3b: n-tile [128,208), 72 valid --------------
// 8 warps, each 16 rows x 80 cols (acc[5])
__global__ __launch_bounds__(256, 2) void g3b(const float* __restrict__ b3,
                                              float* __restrict__ out) {
    extern __shared__ __align__(16) char dsm[];
    const int tid = threadIdx.x, wid = tid >> 5;
    const int j3 = blockIdx.z, m0 = blockIdx.y * 128;
    const uint32_t sbase = smem_u32(dsm);

    const __half* aS = g_h2r + ((size_t)(j3 * 1024 + m0)) * 1024;
    const __half* bS = g_k3t + ((size_t)(j3 * 256 + 128)) * 1024;

    // A @ 0/14336, B(80 rows) @ 28672/37632; total 46592
    wmma::fragment<wmma::accumulator, 16, 16, 16, float> acc[5];
#pragma unroll
    for (int j = 0; j < 5; j++) wmma::fill_fragment(acc[j], 0.0f);

    for (int i = tid; i < 512; i += 256) {
        int row = i >> 2, seg = i & 3;
        cpa(sbase + row * ROWB + seg * 16, aS + row * 1024 + seg * 8);
    }
    for (int i = tid; i < 320; i += 256) {
        int row = i >> 2, seg = i & 3;
        cpa(sbase + 28672 + row * ROWB + seg * 16, bS + row * 1024 + seg * 8);
    }
    cpcommit();

    for (int c = 0; c < 32; c++) {
        const int buf = c & 1;
        if (c + 1 < 32) {
            const int nb = (c + 1) & 1, k0 = (c + 1) * 32;
            for (int i = tid; i < 512; i += 256) {
                int row = i >> 2, seg = i & 3;
                cpa(sbase + nb * 14336 + row * ROWB + seg * 16,
                    aS + row * 1024 + k0 + seg * 8);
            }
            for (int i = tid; i < 320; i += 256) {
                int row = i >> 2, seg = i & 3;
                cpa(sbase + 28672 + nb * 8960 + row * ROWB + seg * 16,
                    bS + row * 1024 + k0 + seg * 8);
            }
            cpcommit();
            cpwait1();
        } else {
            cpwait0();
        }
        __syncthreads();

        const __half* As = (const __half*)(dsm + buf * 14336);
        const __half* Bs = (const __half*)(dsm + 28672 + buf * 8960);
#pragma unroll
        for (int kk = 0; kk < 32; kk += 16) {
            wmma::fragment<wmma::matrix_a, 16, 16, 16, __half, wmma::row_major> af;
            wmma::fragment<wmma::matrix_b, 16, 16, 16, __half, wmma::col_major> bf[5];
            wmma::load_matrix_sync(af, As + (wid * 16) * LDM + kk, LDM);
#pragma unroll
            for (int j = 0; j < 5; j++)
                wmma::load_matrix_sync(bf[j], Bs + (j * 16) * LDM + kk, LDM);
#pragma unroll
            for (int j = 0; j < 5; j++)
                wmma::mma_sync(acc[j], af, bf[j], acc[j]);
        }
        __syncthreads();
    }

    float* stage = (float*)dsm;   // [128][84] fp32 = 43008 B
#pragma unroll
    for (int j = 0; j < 5; j++)
        wmma::store_matrix_sync(stage + (wid * 16) * 84 + j * 16,
                                acc[j], 84, wmma::mem_row_major);
    __syncthreads();
    const int b2x = j3 >> 3, b2y = j3 & 7;
    for (int e = tid; e < 128 * 72; e += 256) {
        int cc = e % 72, row = e / 72;
        int l3 = 128 + cc;
        float v = stage[row * 84 + cc] + b3[j3 * 200 + l3];
        int q = l3 >> 1, c = l3 & 1;
        int w2x = q / 10, w2y = q - w2x * 10;
        out[(m0 + row) * 12800 +
            ((b2x * 10 + w2x) * 80 + b2y * 10 + w2y) * 2 + c] = v;
    }
}

extern "C" void kernel_launch(void* const* d_in, const int* in_sizes, int n_in,
                              void* d_out, int out_size) {
    const float* x   = (const float*)d_in[0];
    const float* k1  = (const float*)d_in[1];
    const float* b1  = (const float*)d_in[2];
    const float* k2  = (const float*)d_in[3];
    const float* b2  = (const float*)d_in[4];
    const float* k3w = (const float*)d_in[5];
    const float* b3  = (const float*)d_in[6];
    float* out = (float*)d_out;

    cudaFuncSetAttribute(g1,  cudaFuncAttributeMaxDynamicSharedMemorySize, 88064);
    cudaFuncSetAttribute(g3a, cudaFuncAttributeMaxDynamicSharedMemorySize, 57344);
    cudaFuncSetAttribute(g3b, cudaFuncAttributeMaxDynamicSharedMemorySize, 46592);

    gather_x    <<<dim3(1024, 8), 256>>>(x);
    transpose_k1<<<dim3(32, 7, 64), dim3(32, 8)>>>(k1);
    transpose_k3<<<dim3(32, 7, 64), dim3(32, 8)>>>(k3w);
    g1 <<<dim3(8, 8, 64), 256, 88064>>>(b1);
    g2 <<<dim3(4096, 8), 128>>>(k2, b2);
    g3a<<<dim3(1, 8, 64), 256, 57344>>>(b3, out);
    g3b<<<dim3(1, 8, 64), 256, 46592>>>(b3, out);
}